// round 6
// baseline (speedup 1.0000x reference)
#include <cuda_runtime.h>
#include <cstdint>

// ---------------------------------------------------------------------------
// QuadConv via baseline-PTX tf32 mma.sync + ldmatrix (virtual arch compute_103:
// no tcgen05/TMEM features survive ptxas).
//
//   out[N,128] = concat_k( F[idx[:,k]] ) @ W^T + b
//   N=262144, C_IN=128, C_OUT=128, K=9  ->  GEMM M=N, N=128, K=1152.
//   neigh_idx is int32 on the wire (JAX x64 disabled).
//
// R5: feed-path overhaul.
//  - W pre-converted to tf32 once per launch (tiny pre-kernel, __device__ buf)
//  - A converted to tf32 in smem once per element (by its own loader thread)
//  - fragments fetched with ldmatrix.m8n8.x4.b16 (1 instr per 16x8 A frag,
//    1 instr per two 8x8 B frags) -> inner loop is ldmatrix + HMMA only.
// ---------------------------------------------------------------------------

namespace qc {
constexpr int NPTS   = 262144;
constexpr int CIN    = 128;
constexpr int COUT   = 128;
constexpr int KNB    = 9;
constexpr int KTOT   = KNB * CIN;      // 1152
constexpr int NKB    = KTOT / 32;      // 36 k-blocks of 32
constexpr int MTILE  = 256;
constexpr int CTAS   = NPTS / MTILE;   // 1024
constexpr int THREADS = 512;

constexpr int ROWPAD = 36;             // floats per smem row (32 + 4 pad); 144B, 16B-aligned
constexpr int A_FLOATS   = MTILE * ROWPAD;      // 9216 per buffer
constexpr int B_FLOATS   = COUT * ROWPAD;       // 4608 per buffer
constexpr int OFF_A      = 0;                   // 2 buffers
constexpr int OFF_B      = 2 * A_FLOATS;        // 2 buffers
constexpr int OFF_IDX    = OFF_B + 2 * B_FLOATS;
constexpr int OFF_BIAS   = OFF_IDX + KNB * MTILE;
constexpr int SMEM_FLOATS = OFF_BIAS + COUT;
constexpr int SMEM_BYTES  = SMEM_FLOATS * 4;    // 120320
} // namespace qc

// W pre-converted to tf32 (RNA) once per launch. Static device scratch.
__device__ uint32_t W_TF32[qc::COUT * qc::KTOT];

// ------------------------------ PTX helpers -------------------------------

__device__ __forceinline__ uint32_t smem_u32(const void* p) {
    return (uint32_t)__cvta_generic_to_shared(p);
}

__device__ __forceinline__ void cp_async16(uint32_t dst, const void* src, int src_size) {
    asm volatile("cp.async.cg.shared.global [%0], [%1], 16, %2;"
                 ::"r"(dst), "l"(src), "r"(src_size) : "memory");
}
__device__ __forceinline__ void cp_commit() {
    asm volatile("cp.async.commit_group;" ::: "memory");
}
template <int N>
__device__ __forceinline__ void cp_wait() {
    asm volatile("cp.async.wait_group %0;" ::"n"(N) : "memory");
}

__device__ __forceinline__ uint32_t f2tf32(float f) {
    uint32_t u;
    asm("cvt.rna.tf32.f32 %0, %1;" : "=r"(u) : "f"(f));
    return u;
}

__device__ __forceinline__ void ldmatrix_x4(uint32_t& r0, uint32_t& r1,
                                            uint32_t& r2, uint32_t& r3, uint32_t addr) {
    asm volatile("ldmatrix.sync.aligned.m8n8.x4.shared.b16 {%0,%1,%2,%3}, [%4];"
                 : "=r"(r0), "=r"(r1), "=r"(r2), "=r"(r3) : "r"(addr));
}

__device__ __forceinline__ void mma_tf32(float& c0, float& c1, float& c2, float& c3,
                                         uint32_t a0, uint32_t a1, uint32_t a2, uint32_t a3,
                                         uint32_t b0, uint32_t b1) {
    asm volatile(
        "mma.sync.aligned.m16n8k8.row.col.f32.tf32.tf32.f32 "
        "{%0,%1,%2,%3}, {%4,%5,%6,%7}, {%8,%9}, {%0,%1,%2,%3};"
        : "+f"(c0), "+f"(c1), "+f"(c2), "+f"(c3)
        : "r"(a0), "r"(a1), "r"(a2), "r"(a3), "r"(b0), "r"(b1));
}

// ----------------------- pre-kernel: W -> tf32 -----------------------------

__global__ void wconv_kernel(const float* __restrict__ W) {
    int i = blockIdx.x * 256 + threadIdx.x;
    if (i < qc::COUT * qc::KTOT) W_TF32[i] = f2tf32(W[i]);
}

// ------------------------------- kernel -----------------------------------

__global__ void __launch_bounds__(qc::THREADS, 1)
quadconv_mma_kernel(const float* __restrict__ F,
                    const int* __restrict__ NIDX,
                    const float* __restrict__ BIAS,
                    float* __restrict__ OUT) {
    using namespace qc;
    extern __shared__ float sm[];
    float* sA    = sm + OFF_A;                 // [2][256][36] (fp32 -> tf32 in place)
    float* sB    = sm + OFF_B;                 // [2][128][36] (tf32 from W_TF32)
    int*   sidx  = (int*)(sm + OFF_IDX);       // [9][256]
    float* sbias = sm + OFF_BIAS;              // [128]

    const uint32_t sA_u = smem_u32(sA);
    const uint32_t sB_u = smem_u32(sB);

    const int tid  = threadIdx.x;
    const int wid  = tid >> 5;
    const int lane = tid & 31;
    const int g    = lane >> 2;   // 0..7
    const int klo  = lane & 3;    // 0..3
    const int gb   = blockIdx.x * MTILE;

    // ---- stage neighbor indices and bias -----------------------------------
    for (int e = tid; e < KNB * MTILE; e += THREADS) {
        int row = e / KNB, kn = e % KNB;
        sidx[kn * MTILE + row] = NIDX[(size_t)(gb + row) * KNB + kn];
    }
    if (tid < COUT) sbias[tid] = BIAS[tid];
    __syncthreads();

    // ---- tile loader: A gather (zfill OOB) + B (pre-converted tf32) --------
    auto load_tiles = [&](int kb, int buf) {
        const int kn   = kb >> 2;
        const int coff = (kb & 3) * 32;
        const int* idxp = sidx + kn * MTILE;
#pragma unroll
        for (int i = 0; i < 4; i++) {
            int e = tid + i * THREADS;
            int row = e >> 3, seg = e & 7;
            int nb  = idxp[row];
            bool ok = (unsigned)nb < (unsigned)NPTS;
            const float* src = F + (size_t)(ok ? nb : 0) * CIN + coff + seg * 4;
            cp_async16(sA_u + (uint32_t)(buf * A_FLOATS + row * ROWPAD + seg * 4) * 4,
                       src, ok ? 16 : 0);
        }
#pragma unroll
        for (int i = 0; i < 2; i++) {
            int e = tid + i * THREADS;
            int n = e >> 3, seg = e & 7;
            const uint32_t* src = W_TF32 + (size_t)n * KTOT + kb * 32 + seg * 4;
            cp_async16(sB_u + (uint32_t)(buf * B_FLOATS + n * ROWPAD + seg * 4) * 4,
                       src, 16);
        }
    };

    // ---- warp tiling: 16 warps 4x4, warp tile 64(M) x 32(N) ----------------
    const int Mbase = (wid >> 2) * 64;
    const int Nbase = (wid & 3) * 32;
    float acc[4][4][4];
#pragma unroll
    for (int mf = 0; mf < 4; mf++)
#pragma unroll
        for (int nf = 0; nf < 4; nf++)
#pragma unroll
            for (int q = 0; q < 4; q++) acc[mf][nf][q] = 0.f;

    // ---- ldmatrix per-lane base offsets (bytes, buffer-relative) -----------
    // A frag (x4): matrix m = lane>>3; row-in-tile = (lane&7) + (m&1)*8; k4 = (m>>1)*4
    const int a_rit = (lane & 7) + ((lane >> 3) & 1) * 8;
    const int a_k4  = (lane >> 4) * 4;
    uint32_t aoff[4];
#pragma unroll
    for (int mf = 0; mf < 4; mf++)
        aoff[mf] = (uint32_t)(((Mbase + mf * 16 + a_rit) * ROWPAD + a_k4) * 4);
    // B frags (x4 covers nf pair): m = lane>>3; n-row = p*16 + (m>>1)*8 + (lane&7);
    // k4 = (m&1)*4
    const int b_nr = ((lane >> 4) & 1) * 8 + (lane & 7);
    const int b_k4 = ((lane >> 3) & 1) * 4;
    uint32_t boff[2];
#pragma unroll
    for (int p = 0; p < 2; p++)
        boff[p] = (uint32_t)(((Nbase + p * 16 + b_nr) * ROWPAD + b_k4) * 4);

    // ---- prologue -----------------------------------------------------------
    load_tiles(0, 0);
    cp_commit();

    // ---- main K loop --------------------------------------------------------
    for (int kb = 0; kb < NKB; kb++) {
        const int buf = kb & 1;
        if (kb + 1 < NKB) {
            load_tiles(kb + 1, buf ^ 1);
            cp_commit();
            cp_wait<1>();
        } else {
            cp_wait<0>();
        }

        // convert exactly the A chunks THIS thread cp.async'd (own-data
        // visibility after wait_group; no barrier needed before this)
        {
            float* Ab = sA + buf * A_FLOATS;
#pragma unroll
            for (int i = 0; i < 4; i++) {
                int e = tid + i * THREADS;
                int row = e >> 3, seg = e & 7;
                float4* p = (float4*)(Ab + row * ROWPAD + seg * 4);
                float4 v = *p;
                uint4 u;
                u.x = f2tf32(v.x); u.y = f2tf32(v.y);
                u.z = f2tf32(v.z); u.w = f2tf32(v.w);
                *(uint4*)p = u;
            }
        }
        __syncthreads();

        const uint32_t abuf = sA_u + (uint32_t)(buf * A_FLOATS) * 4;
        const uint32_t bbuf = sB_u + (uint32_t)(buf * B_FLOATS) * 4;

#pragma unroll
        for (int s = 0; s < 4; s++) {          // 4 k-steps of 8
            uint32_t afr[4][4];
#pragma unroll
            for (int mf = 0; mf < 4; mf++)
                ldmatrix_x4(afr[mf][0], afr[mf][1], afr[mf][2], afr[mf][3],
                            abuf + aoff[mf] + s * 32);
            uint32_t bfr[4][2];
#pragma unroll
            for (int p = 0; p < 2; p++)
                ldmatrix_x4(bfr[2 * p][0], bfr[2 * p][1],
                            bfr[2 * p + 1][0], bfr[2 * p + 1][1],
                            bbuf + boff[p] + s * 32);
#pragma unroll
            for (int mf = 0; mf < 4; mf++)
#pragma unroll
                for (int nf = 0; nf < 4; nf++)
                    mma_tf32(acc[mf][nf][0], acc[mf][nf][1],
                             acc[mf][nf][2], acc[mf][nf][3],
                             afr[mf][0], afr[mf][1], afr[mf][2], afr[mf][3],
                             bfr[nf][0], bfr[nf][1]);
        }
        __syncthreads();   // all reads of buf done before kb+2 overwrites it
    }

    // ---- epilogue: add bias, float2 stores ----------------------------------
#pragma unroll
    for (int mf = 0; mf < 4; mf++) {
#pragma unroll
        for (int nf = 0; nf < 4; nf++) {
            int col  = Nbase + nf * 8 + 2 * klo;
            float bx = sbias[col], by = sbias[col + 1];
            size_t r0 = (size_t)(gb + Mbase + mf * 16 + g) * COUT + col;
            size_t r1 = r0 + (size_t)8 * COUT;
            float2 v0 = make_float2(acc[mf][nf][0] + bx, acc[mf][nf][1] + by);
            float2 v1 = make_float2(acc[mf][nf][2] + bx, acc[mf][nf][3] + by);
            *(float2*)(OUT + r0) = v0;
            *(float2*)(OUT + r1) = v1;
        }
    }
}

// ----------------------------- launch glue --------------------------------

extern "C" void kernel_launch(void* const* d_in, const int* in_sizes, int n_in,
                              void* d_out, int out_size) {
    using namespace qc;
    const float* F = (const float*)d_in[0];
    const int*   I = (const int*)d_in[1];
    const float* W = (const float*)d_in[2];
    const float* B = (const float*)d_in[3];
    for (int i = 0; i < n_in; i++) {
        switch (in_sizes[i]) {
            case NPTS * CIN:       F = (const float*)d_in[i]; break;      // 33554432
            case NPTS * KNB:       I = (const int*)d_in[i];   break;      // 2359296
            case COUT * KNB * CIN: W = (const float*)d_in[i]; break;      // 147456
            case COUT:             B = (const float*)d_in[i]; break;      // 128
            default: break;
        }
    }
    wconv_kernel<<<(COUT * KTOT + 255) / 256, 256>>>(W);
    cudaFuncSetAttribute(quadconv_mma_kernel,
                         cudaFuncAttributeMaxDynamicSharedMemorySize, SMEM_BYTES);
    quadconv_mma_kernel<<<CTAS, THREADS, SMEM_BYTES>>>(F, I, B, (float*)d_out);
}

// round 7
// speedup vs baseline: 1.2763x; 1.2763x over previous
#include <cuda_runtime.h>
#include <cstdint>

// ---------------------------------------------------------------------------
// QuadConv via baseline-PTX tf32 mma.sync + ldmatrix (virtual arch compute_103:
// no tcgen05/TMEM features survive ptxas).
//
//   out[N,128] = concat_k( F[idx[:,k]] ) @ W^T + b
//   N=262144, C_IN=128, C_OUT=128, K=9  ->  GEMM M=N, N=128, K=1152.
//   neigh_idx is int32 on the wire (JAX x64 disabled).
//
// R6: concurrency restructure. R4/R5 both pinned tensor% at ~44 with one
// 512-thread CTA/SM: a single barrier domain serializes gather-wait, convert
// and mma phases across the whole SM. Now: MTILE=128, 256 threads, 2 CTAs/SM
// (smem 78.8KB, regs capped 128) -> two independent pipelines per SM; one
// CTA's mma covers the other's serial phases.
// ---------------------------------------------------------------------------

namespace qc {
constexpr int NPTS   = 262144;
constexpr int CIN    = 128;
constexpr int COUT   = 128;
constexpr int KNB    = 9;
constexpr int KTOT   = KNB * CIN;      // 1152
constexpr int NKB    = KTOT / 32;      // 36 k-blocks of 32
constexpr int MTILE  = 128;
constexpr int CTAS   = NPTS / MTILE;   // 2048
constexpr int THREADS = 256;

constexpr int ROWPAD = 36;             // 32 + 4 pad; 4r mod 32 tiles all banks
constexpr int A_FLOATS   = MTILE * ROWPAD;      // 4608 per buffer
constexpr int B_FLOATS   = COUT * ROWPAD;       // 4608 per buffer
constexpr int OFF_A      = 0;                   // 2 buffers
constexpr int OFF_B      = 2 * A_FLOATS;        // 2 buffers
constexpr int OFF_IDX    = OFF_B + 2 * B_FLOATS;
constexpr int OFF_BIAS   = OFF_IDX + KNB * MTILE;
constexpr int SMEM_FLOATS = OFF_BIAS + COUT;
constexpr int SMEM_BYTES  = SMEM_FLOATS * 4;    // 78,848 -> 2 CTAs/SM
} // namespace qc

// W pre-converted to tf32 (RNA) once per launch. Static device scratch.
__device__ uint32_t W_TF32[qc::COUT * qc::KTOT];

// ------------------------------ PTX helpers -------------------------------

__device__ __forceinline__ uint32_t smem_u32(const void* p) {
    return (uint32_t)__cvta_generic_to_shared(p);
}

__device__ __forceinline__ void cp_async16(uint32_t dst, const void* src, int src_size) {
    asm volatile("cp.async.cg.shared.global [%0], [%1], 16, %2;"
                 ::"r"(dst), "l"(src), "r"(src_size) : "memory");
}
__device__ __forceinline__ void cp_commit() {
    asm volatile("cp.async.commit_group;" ::: "memory");
}
template <int N>
__device__ __forceinline__ void cp_wait() {
    asm volatile("cp.async.wait_group %0;" ::"n"(N) : "memory");
}

__device__ __forceinline__ uint32_t f2tf32(float f) {
    uint32_t u;
    asm("cvt.rna.tf32.f32 %0, %1;" : "=r"(u) : "f"(f));
    return u;
}

__device__ __forceinline__ void ldmatrix_x4(uint32_t& r0, uint32_t& r1,
                                            uint32_t& r2, uint32_t& r3, uint32_t addr) {
    asm volatile("ldmatrix.sync.aligned.m8n8.x4.shared.b16 {%0,%1,%2,%3}, [%4];"
                 : "=r"(r0), "=r"(r1), "=r"(r2), "=r"(r3) : "r"(addr));
}

__device__ __forceinline__ void mma_tf32(float& c0, float& c1, float& c2, float& c3,
                                         uint32_t a0, uint32_t a1, uint32_t a2, uint32_t a3,
                                         uint32_t b0, uint32_t b1) {
    asm volatile(
        "mma.sync.aligned.m16n8k8.row.col.f32.tf32.tf32.f32 "
        "{%0,%1,%2,%3}, {%4,%5,%6,%7}, {%8,%9}, {%0,%1,%2,%3};"
        : "+f"(c0), "+f"(c1), "+f"(c2), "+f"(c3)
        : "r"(a0), "r"(a1), "r"(a2), "r"(a3), "r"(b0), "r"(b1));
}

// ----------------------- pre-kernel: W -> tf32 -----------------------------

__global__ void wconv_kernel(const float* __restrict__ W) {
    int i = blockIdx.x * 256 + threadIdx.x;
    if (i < qc::COUT * qc::KTOT) W_TF32[i] = f2tf32(W[i]);
}

// ------------------------------- kernel -----------------------------------

__global__ void __launch_bounds__(qc::THREADS, 2)
quadconv_mma_kernel(const float* __restrict__ F,
                    const int* __restrict__ NIDX,
                    const float* __restrict__ BIAS,
                    float* __restrict__ OUT) {
    using namespace qc;
    extern __shared__ float sm[];
    float* sA    = sm + OFF_A;                 // [2][128][36] (fp32 -> tf32 in place)
    float* sB    = sm + OFF_B;                 // [2][128][36] (tf32 from W_TF32)
    int*   sidx  = (int*)(sm + OFF_IDX);       // [9][128]
    float* sbias = sm + OFF_BIAS;              // [128]

    const uint32_t sA_u = smem_u32(sA);
    const uint32_t sB_u = smem_u32(sB);

    const int tid  = threadIdx.x;
    const int wid  = tid >> 5;    // 0..7
    const int lane = tid & 31;
    const int g    = lane >> 2;   // 0..7
    const int klo  = lane & 3;    // 0..3
    const int gb   = blockIdx.x * MTILE;

    // ---- stage neighbor indices and bias -----------------------------------
    for (int e = tid; e < KNB * MTILE; e += THREADS) {
        int row = e / KNB, kn = e % KNB;
        sidx[kn * MTILE + row] = NIDX[(size_t)(gb + row) * KNB + kn];
    }
    if (tid < COUT) sbias[tid] = BIAS[tid];
    __syncthreads();

    // ---- tile loader: A gather (zfill OOB) + B (pre-converted tf32) --------
    auto load_tiles = [&](int kb, int buf) {
        const int kn   = kb >> 2;
        const int coff = (kb & 3) * 32;
        const int* idxp = sidx + kn * MTILE;
#pragma unroll
        for (int i = 0; i < 4; i++) {          // A: 1024 chunks / 256 thr
            int e = tid + i * THREADS;
            int row = e >> 3, seg = e & 7;
            int nb  = idxp[row];
            bool ok = (unsigned)nb < (unsigned)NPTS;
            const float* src = F + (size_t)(ok ? nb : 0) * CIN + coff + seg * 4;
            cp_async16(sA_u + (uint32_t)(buf * A_FLOATS + row * ROWPAD + seg * 4) * 4,
                       src, ok ? 16 : 0);
        }
#pragma unroll
        for (int i = 0; i < 4; i++) {          // B: 1024 chunks / 256 thr
            int e = tid + i * THREADS;
            int n = e >> 3, seg = e & 7;
            const uint32_t* src = W_TF32 + (size_t)n * KTOT + kb * 32 + seg * 4;
            cp_async16(sB_u + (uint32_t)(buf * B_FLOATS + n * ROWPAD + seg * 4) * 4,
                       src, 16);
        }
    };

    // ---- warp tiling: 8 warps 2x4, warp tile 64(M) x 32(N) -----------------
    const int Mbase = (wid >> 2) * 64;
    const int Nbase = (wid & 3) * 32;
    float acc[4][4][4];
#pragma unroll
    for (int mf = 0; mf < 4; mf++)
#pragma unroll
        for (int nf = 0; nf < 4; nf++)
#pragma unroll
            for (int q = 0; q < 4; q++) acc[mf][nf][q] = 0.f;

    // ---- ldmatrix per-lane base offsets (bytes, buffer-relative) -----------
    const int a_rit = (lane & 7) + ((lane >> 3) & 1) * 8;
    const int a_k4  = (lane >> 4) * 4;
    uint32_t aoff[4];
#pragma unroll
    for (int mf = 0; mf < 4; mf++)
        aoff[mf] = (uint32_t)(((Mbase + mf * 16 + a_rit) * ROWPAD + a_k4) * 4);
    const int b_nr = ((lane >> 4) & 1) * 8 + (lane & 7);
    const int b_k4 = ((lane >> 3) & 1) * 4;
    uint32_t boff[2];
#pragma unroll
    for (int p = 0; p < 2; p++)
        boff[p] = (uint32_t)(((Nbase + p * 16 + b_nr) * ROWPAD + b_k4) * 4);

    // ---- prologue -----------------------------------------------------------
    load_tiles(0, 0);
    cp_commit();

    // ---- main K loop --------------------------------------------------------
    for (int kb = 0; kb < NKB; kb++) {
        const int buf = kb & 1;
        if (kb + 1 < NKB) {
            load_tiles(kb + 1, buf ^ 1);
            cp_commit();
            cp_wait<1>();
        } else {
            cp_wait<0>();
        }

        // convert exactly the A chunks THIS thread cp.async'd (own-data
        // visibility after wait_group; no barrier needed before this)
        {
            float* Ab = sA + buf * A_FLOATS;
#pragma unroll
            for (int i = 0; i < 4; i++) {
                int e = tid + i * THREADS;
                int row = e >> 3, seg = e & 7;
                float4* p = (float4*)(Ab + row * ROWPAD + seg * 4);
                float4 v = *p;
                uint4 u;
                u.x = f2tf32(v.x); u.y = f2tf32(v.y);
                u.z = f2tf32(v.z); u.w = f2tf32(v.w);
                *(uint4*)p = u;
            }
        }
        __syncthreads();

        const uint32_t abuf = sA_u + (uint32_t)(buf * A_FLOATS) * 4;
        const uint32_t bbuf = sB_u + (uint32_t)(buf * B_FLOATS) * 4;

#pragma unroll
        for (int s = 0; s < 4; s++) {          // 4 k-steps of 8
            uint32_t afr[4][4];
#pragma unroll
            for (int mf = 0; mf < 4; mf++)
                ldmatrix_x4(afr[mf][0], afr[mf][1], afr[mf][2], afr[mf][3],
                            abuf + aoff[mf] + s * 32);
            uint32_t bfr[4][2];
#pragma unroll
            for (int p = 0; p < 2; p++)
                ldmatrix_x4(bfr[2 * p][0], bfr[2 * p][1],
                            bfr[2 * p + 1][0], bfr[2 * p + 1][1],
                            bbuf + boff[p] + s * 32);
#pragma unroll
            for (int mf = 0; mf < 4; mf++)
#pragma unroll
                for (int nf = 0; nf < 4; nf++)
                    mma_tf32(acc[mf][nf][0], acc[mf][nf][1],
                             acc[mf][nf][2], acc[mf][nf][3],
                             afr[mf][0], afr[mf][1], afr[mf][2], afr[mf][3],
                             bfr[nf][0], bfr[nf][1]);
        }
        __syncthreads();   // all reads of buf done before kb+2 overwrites it
    }

    // ---- epilogue: add bias, float2 stores ----------------------------------
#pragma unroll
    for (int mf = 0; mf < 4; mf++) {
#pragma unroll
        for (int nf = 0; nf < 4; nf++) {
            int col  = Nbase + nf * 8 + 2 * klo;
            float bx = sbias[col], by = sbias[col + 1];
            size_t r0 = (size_t)(gb + Mbase + mf * 16 + g) * COUT + col;
            size_t r1 = r0 + (size_t)8 * COUT;
            float2 v0 = make_float2(acc[mf][nf][0] + bx, acc[mf][nf][1] + by);
            float2 v1 = make_float2(acc[mf][nf][2] + bx, acc[mf][nf][3] + by);
            *(float2*)(OUT + r0) = v0;
            *(float2*)(OUT + r1) = v1;
        }
    }
}

// ----------------------------- launch glue --------------------------------

extern "C" void kernel_launch(void* const* d_in, const int* in_sizes, int n_in,
                              void* d_out, int out_size) {
    using namespace qc;
    const float* F = (const float*)d_in[0];
    const int*   I = (const int*)d_in[1];
    const float* W = (const float*)d_in[2];
    const float* B = (const float*)d_in[3];
    for (int i = 0; i < n_in; i++) {
        switch (in_sizes[i]) {
            case NPTS * CIN:       F = (const float*)d_in[i]; break;      // 33554432
            case NPTS * KNB:       I = (const int*)d_in[i];   break;      // 2359296
            case COUT * KNB * CIN: W = (const float*)d_in[i]; break;      // 147456
            case COUT:             B = (const float*)d_in[i]; break;      // 128
            default: break;
        }
    }
    wconv_kernel<<<(COUT * KTOT + 255) / 256, 256>>>(W);
    cudaFuncSetAttribute(quadconv_mma_kernel,
                         cudaFuncAttributeMaxDynamicSharedMemorySize, SMEM_BYTES);
    quadconv_mma_kernel<<<CTAS, THREADS, SMEM_BYTES>>>(F, I, B, (float*)d_out);
}

// round 8
// speedup vs baseline: 1.2948x; 1.0145x over previous
#include <cuda_runtime.h>
#include <cstdint>

// ---------------------------------------------------------------------------
// QuadConv via baseline-PTX tf32 mma.sync + ldmatrix (virtual arch compute_103:
// no tcgen05/TMEM features survive ptxas).
//
//   out[N,128] = concat_k( F[idx[:,k]] ) @ W^T + b
//   N=262144, C_IN=128, C_OUT=128, K=9  ->  GEMM M=N, N=128, K=1152.
//   neigh_idx is int32 on the wire (JAX x64 disabled).
//
// R7: kill the A-convert smem round-trip. A stays raw fp32 in smem; RNA
// rounding to tf32 is done on ldmatrix output fragments with IADD 0x1000
// (tf32 HMMA ignores the low 13 bits; +0x1000 then truncate == cvt.rna).
// Cuts per-kb L1 traffic 164KB -> 132KB and removes the serial convert
// segment. W stays pre-converted (pre-kernel). Numerics bit-identical to R6.
// ---------------------------------------------------------------------------

namespace qc {
constexpr int NPTS   = 262144;
constexpr int CIN    = 128;
constexpr int COUT   = 128;
constexpr int KNB    = 9;
constexpr int KTOT   = KNB * CIN;      // 1152
constexpr int NKB    = KTOT / 32;      // 36 k-blocks of 32
constexpr int MTILE  = 128;
constexpr int CTAS   = NPTS / MTILE;   // 2048
constexpr int THREADS = 256;

constexpr int ROWPAD = 36;             // 32 + 4 pad; conflict-free ldmatrix
constexpr int A_FLOATS   = MTILE * ROWPAD;      // 4608 per buffer
constexpr int B_FLOATS   = COUT * ROWPAD;       // 4608 per buffer
constexpr int OFF_A      = 0;                   // 2 buffers
constexpr int OFF_B      = 2 * A_FLOATS;        // 2 buffers
constexpr int OFF_IDX    = OFF_B + 2 * B_FLOATS;
constexpr int OFF_BIAS   = OFF_IDX + KNB * MTILE;
constexpr int SMEM_FLOATS = OFF_BIAS + COUT;
constexpr int SMEM_BYTES  = SMEM_FLOATS * 4;    // 78,848 -> 2 CTAs/SM
} // namespace qc

// W pre-converted to tf32 (RNA) once per launch. Static device scratch.
__device__ uint32_t W_TF32[qc::COUT * qc::KTOT];

// ------------------------------ PTX helpers -------------------------------

__device__ __forceinline__ uint32_t smem_u32(const void* p) {
    return (uint32_t)__cvta_generic_to_shared(p);
}

__device__ __forceinline__ void cp_async16(uint32_t dst, const void* src, int src_size) {
    asm volatile("cp.async.cg.shared.global [%0], [%1], 16, %2;"
                 ::"r"(dst), "l"(src), "r"(src_size) : "memory");
}
__device__ __forceinline__ void cp_commit() {
    asm volatile("cp.async.commit_group;" ::: "memory");
}
template <int N>
__device__ __forceinline__ void cp_wait() {
    asm volatile("cp.async.wait_group %0;" ::"n"(N) : "memory");
}

__device__ __forceinline__ uint32_t f2tf32(float f) {
    uint32_t u;
    asm("cvt.rna.tf32.f32 %0, %1;" : "=r"(u) : "f"(f));
    return u;
}

__device__ __forceinline__ void ldmatrix_x4(uint32_t& r0, uint32_t& r1,
                                            uint32_t& r2, uint32_t& r3, uint32_t addr) {
    asm volatile("ldmatrix.sync.aligned.m8n8.x4.shared.b16 {%0,%1,%2,%3}, [%4];"
                 : "=r"(r0), "=r"(r1), "=r"(r2), "=r"(r3) : "r"(addr));
}

__device__ __forceinline__ void mma_tf32(float& c0, float& c1, float& c2, float& c3,
                                         uint32_t a0, uint32_t a1, uint32_t a2, uint32_t a3,
                                         uint32_t b0, uint32_t b1) {
    asm volatile(
        "mma.sync.aligned.m16n8k8.row.col.f32.tf32.tf32.f32 "
        "{%0,%1,%2,%3}, {%4,%5,%6,%7}, {%8,%9}, {%0,%1,%2,%3};"
        : "+f"(c0), "+f"(c1), "+f"(c2), "+f"(c3)
        : "r"(a0), "r"(a1), "r"(a2), "r"(a3), "r"(b0), "r"(b1));
}

// ----------------------- pre-kernel: W -> tf32 -----------------------------

__global__ void wconv_kernel(const float* __restrict__ W) {
    int i = blockIdx.x * 256 + threadIdx.x;
    if (i < qc::COUT * qc::KTOT) W_TF32[i] = f2tf32(W[i]);
}

// ------------------------------- kernel -----------------------------------

__global__ void __launch_bounds__(qc::THREADS, 2)
quadconv_mma_kernel(const float* __restrict__ F,
                    const int* __restrict__ NIDX,
                    const float* __restrict__ BIAS,
                    float* __restrict__ OUT) {
    using namespace qc;
    extern __shared__ float sm[];
    float* sA    = sm + OFF_A;                 // [2][128][36] raw fp32 (gathered)
    float* sB    = sm + OFF_B;                 // [2][128][36] tf32 (pre-converted W)
    int*   sidx  = (int*)(sm + OFF_IDX);       // [9][128]
    float* sbias = sm + OFF_BIAS;              // [128]

    const uint32_t sA_u = smem_u32(sA);
    const uint32_t sB_u = smem_u32(sB);

    const int tid  = threadIdx.x;
    const int wid  = tid >> 5;    // 0..7
    const int lane = tid & 31;
    const int g    = lane >> 2;   // 0..7
    const int klo  = lane & 3;    // 0..3
    const int gb   = blockIdx.x * MTILE;

    // ---- stage neighbor indices and bias -----------------------------------
    for (int e = tid; e < KNB * MTILE; e += THREADS) {
        int row = e / KNB, kn = e % KNB;
        sidx[kn * MTILE + row] = NIDX[(size_t)(gb + row) * KNB + kn];
    }
    if (tid < COUT) sbias[tid] = BIAS[tid];
    __syncthreads();

    // ---- tile loader: A gather (zfill OOB, raw fp32) + B (tf32) ------------
    auto load_tiles = [&](int kb, int buf) {
        const int kn   = kb >> 2;
        const int coff = (kb & 3) * 32;
        const int* idxp = sidx + kn * MTILE;
#pragma unroll
        for (int i = 0; i < 4; i++) {          // A: 1024 chunks / 256 thr
            int e = tid + i * THREADS;
            int row = e >> 3, seg = e & 7;
            int nb  = idxp[row];
            bool ok = (unsigned)nb < (unsigned)NPTS;
            const float* src = F + (size_t)(ok ? nb : 0) * CIN + coff + seg * 4;
            cp_async16(sA_u + (uint32_t)(buf * A_FLOATS + row * ROWPAD + seg * 4) * 4,
                       src, ok ? 16 : 0);
        }
#pragma unroll
        for (int i = 0; i < 4; i++) {          // B: 1024 chunks / 256 thr
            int e = tid + i * THREADS;
            int n = e >> 3, seg = e & 7;
            const uint32_t* src = W_TF32 + (size_t)n * KTOT + kb * 32 + seg * 4;
            cp_async16(sB_u + (uint32_t)(buf * B_FLOATS + n * ROWPAD + seg * 4) * 4,
                       src, 16);
        }
    };

    // ---- warp tiling: 8 warps 2x4, warp tile 64(M) x 32(N) -----------------
    const int Mbase = (wid >> 2) * 64;
    const int Nbase = (wid & 3) * 32;
    float acc[4][4][4];
#pragma unroll
    for (int mf = 0; mf < 4; mf++)
#pragma unroll
        for (int nf = 0; nf < 4; nf++)
#pragma unroll
            for (int q = 0; q < 4; q++) acc[mf][nf][q] = 0.f;

    // ---- ldmatrix per-lane base offsets (bytes, buffer-relative) -----------
    const int a_rit = (lane & 7) + ((lane >> 3) & 1) * 8;
    const int a_k4  = (lane >> 4) * 4;
    uint32_t aoff[4];
#pragma unroll
    for (int mf = 0; mf < 4; mf++)
        aoff[mf] = (uint32_t)(((Mbase + mf * 16 + a_rit) * ROWPAD + a_k4) * 4);
    const int b_nr = ((lane >> 4) & 1) * 8 + (lane & 7);
    const int b_k4 = ((lane >> 3) & 1) * 4;
    uint32_t boff[2];
#pragma unroll
    for (int p = 0; p < 2; p++)
        boff[p] = (uint32_t)(((Nbase + p * 16 + b_nr) * ROWPAD + b_k4) * 4);

    // ---- prologue -----------------------------------------------------------
    load_tiles(0, 0);
    cp_commit();

    // ---- main K loop --------------------------------------------------------
    for (int kb = 0; kb < NKB; kb++) {
        const int buf = kb & 1;
        if (kb + 1 < NKB) {
            load_tiles(kb + 1, buf ^ 1);
            cp_commit();
            cp_wait<1>();
        } else {
            cp_wait<0>();
        }
        __syncthreads();   // cross-thread visibility of buf's tiles

        const uint32_t abuf = sA_u + (uint32_t)(buf * A_FLOATS) * 4;
        const uint32_t bbuf = sB_u + (uint32_t)(buf * B_FLOATS) * 4;

#pragma unroll
        for (int s = 0; s < 4; s++) {          // 4 k-steps of 8
            uint32_t afr[4][4];
#pragma unroll
            for (int mf = 0; mf < 4; mf++)
                ldmatrix_x4(afr[mf][0], afr[mf][1], afr[mf][2], afr[mf][3],
                            abuf + aoff[mf] + s * 32);
            uint32_t bfr[4][2];
#pragma unroll
            for (int p = 0; p < 2; p++)
                ldmatrix_x4(bfr[2 * p][0], bfr[2 * p][1],
                            bfr[2 * p + 1][0], bfr[2 * p + 1][1],
                            bbuf + boff[p] + s * 32);
            // RNA-to-tf32 on raw fp32 A fragments: +0x1000, HW truncates
            // the low 13 bits. Bit-identical to cvt.rna.tf32.
#pragma unroll
            for (int mf = 0; mf < 4; mf++) {
                afr[mf][0] += 0x1000u; afr[mf][1] += 0x1000u;
                afr[mf][2] += 0x1000u; afr[mf][3] += 0x1000u;
            }
#pragma unroll
            for (int mf = 0; mf < 4; mf++)
#pragma unroll
                for (int nf = 0; nf < 4; nf++)
                    mma_tf32(acc[mf][nf][0], acc[mf][nf][1],
                             acc[mf][nf][2], acc[mf][nf][3],
                             afr[mf][0], afr[mf][1], afr[mf][2], afr[mf][3],
                             bfr[nf][0], bfr[nf][1]);
        }
        __syncthreads();   // all reads of buf done before kb+2 overwrites it
    }

    // ---- epilogue: add bias, float2 stores ----------------------------------
#pragma unroll
    for (int mf = 0; mf < 4; mf++) {
#pragma unroll
        for (int nf = 0; nf < 4; nf++) {
            int col  = Nbase + nf * 8 + 2 * klo;
            float bx = sbias[col], by = sbias[col + 1];
            size_t r0 = (size_t)(gb + Mbase + mf * 16 + g) * COUT + col;
            size_t r1 = r0 + (size_t)8 * COUT;
            float2 v0 = make_float2(acc[mf][nf][0] + bx, acc[mf][nf][1] + by);
            float2 v1 = make_float2(acc[mf][nf][2] + bx, acc[mf][nf][3] + by);
            *(float2*)(OUT + r0) = v0;
            *(float2*)(OUT + r1) = v1;
        }
    }
}

// ----------------------------- launch glue --------------------------------

extern "C" void kernel_launch(void* const* d_in, const int* in_sizes, int n_in,
                              void* d_out, int out_size) {
    using namespace qc;
    const float* F = (const float*)d_in[0];
    const int*   I = (const int*)d_in[1];
    const float* W = (const float*)d_in[2];
    const float* B = (const float*)d_in[3];
    for (int i = 0; i < n_in; i++) {
        switch (in_sizes[i]) {
            case NPTS * CIN:       F = (const float*)d_in[i]; break;      // 33554432
            case NPTS * KNB:       I = (const int*)d_in[i];   break;      // 2359296
            case COUT * KNB * CIN: W = (const float*)d_in[i]; break;      // 147456
            case COUT:             B = (const float*)d_in[i]; break;      // 128
            default: break;
        }
    }
    wconv_kernel<<<(COUT * KTOT + 255) / 256, 256>>>(W);
    cudaFuncSetAttribute(quadconv_mma_kernel,
                         cudaFuncAttributeMaxDynamicSharedMemorySize, SMEM_BYTES);
    quadconv_mma_kernel<<<CTAS, THREADS, SMEM_BYTES>>>(F, I, B, (float*)d_out);
}